// round 13
// baseline (speedup 1.0000x reference)
#include <cuda_runtime.h>
#include <cuda_fp16.h>
#include <math.h>

#define N_NODES 50000
#define N_EDGES 1600000
#define D 128
#define BN_EPS 1e-5f
#define NB 196   // scan blocks: 196*256 = 50176 >= N_NODES

// ---------------- device scratch (no allocations allowed) ----------------
__device__ __align__(16) float  g_hws[N_NODES * D];   // (h @ W) * dinv[row], fp32
__device__ __align__(16) __half g_hws_h[N_NODES * D]; // same, fp16 (gather copy)
__device__ __align__(16) float  g_agg[N_NODES * D];   // pre-BN activations
__device__ __align__(16) float4 g_Wp[3 * 8 * 128 * 8];// W pre-split, fragment-packed
__device__ int   g_src[N_EDGES];
__device__ int   g_dst[N_EDGES];
__device__ int   g_is_i32 = 0;                        // set-only dtype flag
__device__ int   g_deg[N_NODES];
__device__ int   g_rowstart[N_NODES + 1];
__device__ int   g_cursor[N_NODES];
__device__ int   g_csr_src[N_EDGES];
__device__ int   g_blocksum[NB];
__device__ int   g_blockoff[NB];
__device__ float g_dinv[N_NODES];                     // rsqrt(deg+2)
__device__ float g_colsum[D];
__device__ float g_colsq[D];
__device__ float g_scale[D];
__device__ float g_shift[D];

// ---------------- tf32 helpers (fragment layout verified R6/R11) -----------
__device__ __forceinline__ unsigned f2tf32(float x) {
    unsigned r;
    asm("cvt.rna.tf32.f32 %0, %1;" : "=r"(r) : "f"(x));
    return r;
}
__device__ __forceinline__ void mma_tf32(float c[4], const unsigned a[4],
                                         unsigned b0, unsigned b1) {
    asm volatile(
        "mma.sync.aligned.m16n8k8.row.col.f32.tf32.tf32.f32 "
        "{%0,%1,%2,%3}, {%4,%5,%6,%7}, {%8,%9}, {%0,%1,%2,%3};"
        : "+f"(c[0]), "+f"(c[1]), "+f"(c[2]), "+f"(c[3])
        : "r"(a[0]), "r"(a[1]), "r"(a[2]), "r"(a[3]), "r"(b0), "r"(b1));
}

// ---------------- input canonicalization + degree zero ----------------
__global__ void detect_kernel(const int* __restrict__ p32) {
    int i = blockIdx.x * blockDim.x + threadIdx.x;
    if (i < N_NODES) g_deg[i] = 0;
    if (i < 8192 && p32[2 * i + 1] != 0) g_is_i32 = 1;
}

__global__ void convert_count_kernel(const void* __restrict__ eiv) {
    int e = blockIdx.x * blockDim.x + threadIdx.x;
    if (e >= N_EDGES) return;
    int s, d;
    if (g_is_i32) {
        const int* p = (const int*)eiv;
        s = p[e]; d = p[N_EDGES + e];
    } else {
        const long long* p = (const long long*)eiv;
        s = (int)p[e]; d = (int)p[N_EDGES + e];
    }
    g_src[e] = s;
    g_dst[e] = d;
    atomicAdd(&g_deg[d], 1);
}

// ---- grid scan A: block-local exclusive scan + dinv + W fragment pre-pack --
__global__ void scanA_kernel(const float* __restrict__ W0,
                             const float* __restrict__ W1,
                             const float* __restrict__ W2) {
    __shared__ int wsum[8];
    const int tid = threadIdx.x, lane = tid & 31, w = tid >> 5;
    const int i = blockIdx.x * 256 + tid;
    int v = (i < N_NODES) ? g_deg[i] : 0;
    int x = v;
#pragma unroll
    for (int off = 1; off < 32; off <<= 1) {
        int n = __shfl_up_sync(0xffffffffu, x, off);
        if (lane >= off) x += n;
    }
    if (lane == 31) wsum[w] = x;
    __syncthreads();
    if (w == 0) {
        int t = (lane < 8) ? wsum[lane] : 0;
#pragma unroll
        for (int off = 1; off < 8; off <<= 1) {
            int n = __shfl_up_sync(0xffffffffu, t, off);
            if (lane >= off) t += n;
        }
        if (lane < 8) wsum[lane] = t;
    }
    __syncthreads();
    int wpre = (w == 0) ? 0 : wsum[w - 1];
    if (i < N_NODES) {
        g_rowstart[i] = x - v + wpre;
        g_dinv[i] = rsqrtf((float)v + 2.0f);
    }
    if (tid == 255) g_blocksum[blockIdx.x] = x + wpre;

    // ---- W fragment pre-pack: gid -> (l, s, n, q) ----
    // g_Wp[((l*8+s)*128+n)*8+q] = {Wh[k][n], Wh[k+4][n], Wl[k][n], Wl[k+4][n]}
    // with k = s*16 + (q>>2)*8 + (q&3)
    int gid = blockIdx.x * 256 + tid;
    if (gid < 3 * 8 * 128 * 8) {
        int q = gid & 7;
        int n = (gid >> 3) & 127;
        int s = (gid >> 10) & 7;
        int l = gid >> 13;
        const float* Wl = (l == 0) ? W0 : ((l == 1) ? W1 : W2);
        int k = s * 16 + ((q >> 2) << 3) + (q & 3);
        float w0 = Wl[k * D + n];
        float w1 = Wl[(k + 4) * D + n];
        float h0 = __uint_as_float(f2tf32(w0));
        float h1 = __uint_as_float(f2tf32(w1));
        g_Wp[gid] = make_float4(h0, h1,
                                __uint_as_float(f2tf32(w0 - h0)),
                                __uint_as_float(f2tf32(w1 - h1)));
    }
}

__global__ void scanB_kernel() {
    __shared__ int wsum[8];
    const int tid = threadIdx.x, lane = tid & 31, w = tid >> 5;
    int v = (tid < NB) ? g_blocksum[tid] : 0;
    int x = v;
#pragma unroll
    for (int off = 1; off < 32; off <<= 1) {
        int n = __shfl_up_sync(0xffffffffu, x, off);
        if (lane >= off) x += n;
    }
    if (lane == 31) wsum[w] = x;
    __syncthreads();
    if (w == 0) {
        int t = (lane < 8) ? wsum[lane] : 0;
#pragma unroll
        for (int off = 1; off < 8; off <<= 1) {
            int n = __shfl_up_sync(0xffffffffu, t, off);
            if (lane >= off) t += n;
        }
        if (lane < 8) wsum[lane] = t;
    }
    __syncthreads();
    int wpre = (w == 0) ? 0 : wsum[w - 1];
    if (tid < NB) g_blockoff[tid] = x - v + wpre;
    if (tid == 255) g_rowstart[N_NODES] = x + wpre;
}

__global__ void scanC_kernel() {
    int i = blockIdx.x * 256 + threadIdx.x;
    if (i < N_NODES) {
        int rs = g_rowstart[i] + g_blockoff[blockIdx.x];
        g_rowstart[i] = rs;
        g_cursor[i] = rs;
    }
}

__global__ void fill_kernel() {
    int e = blockIdx.x * blockDim.x + threadIdx.x;
    if (e < N_EDGES) {
        int p = atomicAdd(&g_cursor[g_dst[e]], 1);
        g_csr_src[p] = g_src[e];
    }
}

// ---------------- split-tf32 tensor GEMM, fragment-packed smem --------------
// Tile 64 rows x 128 cols, 256 threads = 8 warps (rg=w&3 rows, cg=w>>2 cols).
// K sliced 16-deep. A smem: float2(hi,lo), stride 20 (16-lane phase
// conflict-free). W smem: float4(b0h,b1h,b0l,b1l) per (n, k-quad), stride 12
// (8-lane octet conflict-free). 3xTF32 = hi*hi + hi*lo + lo*hi.
__global__ void __launch_bounds__(256, 3) gemm_kernel(const float* __restrict__ A,
                                                      int layer, int mode) {
    __shared__ float2 sA[64][20];
    __shared__ float4 sW[128][12];
    __shared__ float s_scale[D], s_shift[D];

    const int tid = threadIdx.x;
    const int rb = blockIdx.x * 64;
    const int lane = tid & 31, w = tid >> 5;
    const int rg = w & 3, cg = w >> 2;
    const int gi = lane >> 2, t4 = lane & 3;

    if (mode && tid < D) { s_scale[tid] = g_scale[tid]; s_shift[tid] = g_shift[tid]; }
    if (blockIdx.x == 0 && tid < D) { g_colsum[tid] = 0.0f; g_colsq[tid] = 0.0f; }
    __syncthreads();   // s_scale/s_shift visible before any staging read

    float c[8][4];
#pragma unroll
    for (int n0 = 0; n0 < 8; n0++)
#pragma unroll
        for (int j = 0; j < 4; j++) c[n0][j] = 0.0f;

    // staging roles
    const int a_row = tid >> 2;          // 0..63
    const int a_kp = (tid & 3) * 4;      // 0,4,8,12
    const int grow = rb + a_row;
    const int w_q = tid & 7;             // quad 0..7
    const int w_n4 = tid >> 3;           // n-group 0..31
    const float* __restrict__ srcA = mode ? g_agg : A;
    const float4* __restrict__ Wp = g_Wp + layer * 8192;

    for (int s = 0; s < 8; s++) {
        const int kk = s * 16;
        // ---- stage A (64 x 16): split hi/lo into float2 ----
        {
            float4 a = make_float4(0.f, 0.f, 0.f, 0.f);
            if (grow < N_NODES) {
                a = *(const float4*)&srcA[grow * D + kk + a_kp];
                if (mode) {
                    int cb = kk + a_kp;
                    a.x = fmaxf(a.x * s_scale[cb + 0] + s_shift[cb + 0], 0.f);
                    a.y = fmaxf(a.y * s_scale[cb + 1] + s_shift[cb + 1], 0.f);
                    a.z = fmaxf(a.z * s_scale[cb + 2] + s_shift[cb + 2], 0.f);
                    a.w = fmaxf(a.w * s_scale[cb + 3] + s_shift[cb + 3], 0.f);
                }
            }
            float hx = __uint_as_float(f2tf32(a.x));
            float hy = __uint_as_float(f2tf32(a.y));
            float hz = __uint_as_float(f2tf32(a.z));
            float hw = __uint_as_float(f2tf32(a.w));
            sA[a_row][a_kp + 0] = make_float2(hx, __uint_as_float(f2tf32(a.x - hx)));
            sA[a_row][a_kp + 1] = make_float2(hy, __uint_as_float(f2tf32(a.y - hy)));
            sA[a_row][a_kp + 2] = make_float2(hz, __uint_as_float(f2tf32(a.z - hz)));
            sA[a_row][a_kp + 3] = make_float2(hw, __uint_as_float(f2tf32(a.w - hw)));
        }
        // ---- stage W (128 n x 8 q): pre-packed, straight copy ----
#pragma unroll
        for (int i = 0; i < 4; i++) {
            int n = w_n4 * 4 + i;
            sW[n][w_q] = Wp[(s * 128 + n) * 8 + w_q];
        }
        __syncthreads();

        // ---- compute: 2 k-steps of 8 ----
#pragma unroll
        for (int ks = 0; ks < 2; ks++) {
            const int k = ks * 8 + t4;
            const int r0 = rg * 16 + gi, r1 = r0 + 8;
            float2 a00 = sA[r0][k];
            float2 a10 = sA[r1][k];
            float2 a01 = sA[r0][k + 4];
            float2 a11 = sA[r1][k + 4];
            unsigned ah[4] = {__float_as_uint(a00.x), __float_as_uint(a10.x),
                              __float_as_uint(a01.x), __float_as_uint(a11.x)};
            unsigned al[4] = {__float_as_uint(a00.y), __float_as_uint(a10.y),
                              __float_as_uint(a01.y), __float_as_uint(a11.y)};
            const int q = ks * 4 + t4;
#pragma unroll
            for (int n0 = 0; n0 < 8; n0++) {
                float4 b = sW[cg * 64 + n0 * 8 + gi][q];
                unsigned b0h = __float_as_uint(b.x), b1h = __float_as_uint(b.y);
                unsigned b0l = __float_as_uint(b.z), b1l = __float_as_uint(b.w);
                mma_tf32(c[n0], ah, b0h, b1h);   // hi*hi
                mma_tf32(c[n0], ah, b0l, b1l);   // hi*lo
                mma_tf32(c[n0], al, b0h, b1h);   // lo*hi
            }
        }
        __syncthreads();
    }

    // ---- epilogue: c0=(r0,n) c1=(r0,n+1) c2=(r0+8,n) c3=(r0+8,n+1) ----
    const int row0 = rb + rg * 16 + gi;
    const int row1 = row0 + 8;
    const float di0 = (row0 < N_NODES) ? g_dinv[row0] : 0.0f;
    const float di1 = (row1 < N_NODES) ? g_dinv[row1] : 0.0f;
    __half2* hout = reinterpret_cast<__half2*>(g_hws_h);
#pragma unroll
    for (int n0 = 0; n0 < 8; n0++) {
        int n = cg * 64 + n0 * 8 + 2 * t4;
        int hc = n >> 1;
        if (row0 < N_NODES) {
            float2 v = make_float2(c[n0][0] * di0, c[n0][1] * di0);
            *(float2*)&g_hws[row0 * D + n] = v;
            hout[row0 * (D / 2) + hc] = __floats2half2_rn(v.x, v.y);
        }
        if (row1 < N_NODES) {
            float2 v = make_float2(c[n0][2] * di1, c[n0][3] * di1);
            *(float2*)&g_hws[row1 * D + n] = v;
            hout[row1 * (D / 2) + hc] = __floats2half2_rn(v.x, v.y);
        }
    }
}

// ---------------- aggregate (warp per node, fp16 gathers) -------------------
__global__ void aggregate_kernel(const float* __restrict__ b) {
    const int node = blockIdx.x * 8 + (threadIdx.x >> 5);
    const int lane = threadIdx.x & 31;
    if (node >= N_NODES) return;

    const int beg = g_rowstart[node];
    const int end = g_rowstart[node + 1];
    const uint2* __restrict__ hh = reinterpret_cast<const uint2*>(g_hws_h);

    float4 acc = make_float4(0.0f, 0.0f, 0.0f, 0.0f);
    for (int k0 = beg; k0 < end; k0 += 32) {
        int t = k0 + lane;
        int idx = (t < end) ? g_csr_src[t] : 0;
        int m = min(32, end - k0);
#pragma unroll 8
        for (int j = 0; j < m; j++) {
            int s = __shfl_sync(0xffffffffu, idx, j);
            uint2 raw = hh[s * 32 + lane];
            float2 f0 = __half22float2(*reinterpret_cast<__half2*>(&raw.x));
            float2 f1 = __half22float2(*reinterpret_cast<__half2*>(&raw.y));
            acc.x += f0.x; acc.y += f0.y; acc.z += f1.x; acc.w += f1.y;
        }
    }

    const float4* __restrict__ hws4 = reinterpret_cast<const float4*>(g_hws);
    float4 self = hws4[node * 32 + lane];
    float dinv = g_dinv[node];
    float4 b4 = reinterpret_cast<const float4*>(b)[lane];
    float4 o;
    o.x = dinv * (acc.x + 2.0f * self.x) + b4.x;
    o.y = dinv * (acc.y + 2.0f * self.y) + b4.y;
    o.z = dinv * (acc.z + 2.0f * self.z) + b4.z;
    o.w = dinv * (acc.w + 2.0f * self.w) + b4.w;
    reinterpret_cast<float4*>(g_agg)[node * 32 + lane] = o;
}

// column sums/sumsq over g_agg; block handles 128 rows (thread = column)
__global__ void stats_kernel() {
    const int c = threadIdx.x;
    const int r0 = blockIdx.x * 128;
    float s = 0.0f, sq = 0.0f;
    for (int i = 0; i < 128; i++) {
        int r = r0 + i;
        if (r >= N_NODES) break;
        float v = g_agg[r * D + c];
        s += v;
        sq += v * v;
    }
    atomicAdd(&g_colsum[c], s);
    atomicAdd(&g_colsq[c], sq);
}

__global__ void bn_final_kernel(const float* __restrict__ gamma,
                                const float* __restrict__ beta) {
    int c = threadIdx.x;
    float mean = g_colsum[c] * (1.0f / (float)N_NODES);
    float var = g_colsq[c] * (1.0f / (float)N_NODES) - mean * mean;
    float sc = gamma[c] * rsqrtf(var + BN_EPS);
    g_scale[c] = sc;
    g_shift[c] = beta[c] - mean * sc;
}

// final layer only: out = relu(agg*scale + shift)
__global__ void apply_kernel(float* __restrict__ out) {
    int idx = blockIdx.x * blockDim.x + threadIdx.x;
    if (idx >= N_NODES * D) return;
    int c = idx & (D - 1);
    float v = g_agg[idx] * g_scale[c] + g_shift[c];
    out[idx] = fmaxf(v, 0.0f);
}

// ---------------- launch ----------------
extern "C" void kernel_launch(void* const* d_in, const int* in_sizes, int n_in,
                              void* d_out, int out_size) {
    const float* x = (const float*)d_in[0];
    const void* ei = d_in[1];
    const float* W[3]  = {(const float*)d_in[2],  (const float*)d_in[6],  (const float*)d_in[10]};
    const float* bb[3] = {(const float*)d_in[3],  (const float*)d_in[7],  (const float*)d_in[11]};
    const float* gg[3] = {(const float*)d_in[4],  (const float*)d_in[8],  (const float*)d_in[12]};
    const float* be[3] = {(const float*)d_in[5],  (const float*)d_in[9],  (const float*)d_in[13]};
    float* out = (float*)d_out;

    const int eblocks = (N_EDGES + 255) / 256;
    const int gemm_blocks = (N_NODES + 63) / 64;
    const int agg_blocks = (N_NODES + 7) / 8;
    const int stats_blocks = (N_NODES + 127) / 128;
    const int app_blocks = (N_NODES * D + 255) / 256;

    detect_kernel<<<NB, 256>>>((const int*)ei);                 // 1
    convert_count_kernel<<<eblocks, 256>>>(ei);                 // 2
    scanA_kernel<<<NB, 256>>>(W[0], W[1], W[2]);                // 3 (dinv + W pack)
    gemm_kernel<<<gemm_blocks, 256>>>(x, 0, 0);                 // 4 <- ncu slot
    scanB_kernel<<<1, 256>>>();                                 // 5
    scanC_kernel<<<NB, 256>>>();                                // 6
    fill_kernel<<<eblocks, 256>>>();                            // 7

    for (int layer = 0; layer < 3; layer++) {
        if (layer > 0)
            gemm_kernel<<<gemm_blocks, 256>>>(x, layer, 1);
        aggregate_kernel<<<agg_blocks, 256>>>(bb[layer]);
        stats_kernel<<<stats_blocks, 128>>>();
        bn_final_kernel<<<1, D>>>(gg[layer], be[layer]);
    }
    apply_kernel<<<app_blocks, 256>>>(out);
}